// round 5
// baseline (speedup 1.0000x reference)
#include <cuda_runtime.h>
#include <cuda_bf16.h>
#include <cstdint>
#include <math_constants.h>

typedef unsigned int u32;

#define BATCH 4
#define NTOK  2304
#define DIM   2048
#define VDIM  1024
#define MTOT  (BATCH * NTOK)   // 9216

// ----------------------------- scratch (allocation-free rule) ---------------
__device__ __nv_bfloat16 g_fh[(size_t)MTOT * DIM];
__device__ __nv_bfloat16 g_fl[(size_t)MTOT * DIM];
__device__ __nv_bfloat16 g_wqh[(size_t)DIM * DIM];
__device__ __nv_bfloat16 g_wql[(size_t)DIM * DIM];
__device__ __nv_bfloat16 g_wkh[(size_t)DIM * DIM];
__device__ __nv_bfloat16 g_wkl[(size_t)DIM * DIM];
__device__ __nv_bfloat16 g_wuh[(size_t)VDIM * DIM];
__device__ __nv_bfloat16 g_wul[(size_t)VDIM * DIM];
__device__ __nv_bfloat16 g_qh[(size_t)MTOT * DIM];
__device__ __nv_bfloat16 g_ql[(size_t)MTOT * DIM];
__device__ __nv_bfloat16 g_kh[(size_t)MTOT * DIM];
__device__ __nv_bfloat16 g_kl[(size_t)MTOT * DIM];
__device__ __nv_bfloat16 g_vth[(size_t)VDIM * MTOT];   // v^T [VDIM, MTOT]
__device__ __nv_bfloat16 g_vtl[(size_t)VDIM * MTOT];
__device__ float         g_adj[(size_t)BATCH * NTOK * NTOK];
__device__ __nv_bfloat16 g_ph[(size_t)BATCH * NTOK * NTOK];
__device__ __nv_bfloat16 g_pl[(size_t)BATCH * NTOK * NTOK];

// ----------------------------- helpers --------------------------------------
__device__ __forceinline__ u32 smem_u32(const void* p) {
    u32 a;
    asm("{ .reg .u64 t; cvta.to.shared.u64 t, %1; cvt.u32.u64 %0, t; }"
        : "=r"(a) : "l"(p));
    return a;
}

__device__ __forceinline__ void ldgsts16(u32 dst, const void* src) {
    asm volatile("cp.async.cg.shared.global [%0], [%1], 16;"
                 :: "r"(dst), "l"(src) : "memory");
}
#define CP_COMMIT() asm volatile("cp.async.commit_group;" ::: "memory")
#define CP_WAIT(n)  asm volatile("cp.async.wait_group %0;" :: "n"(n) : "memory")

__device__ __forceinline__ void ldsm4(u32 addr, u32& r0, u32& r1, u32& r2, u32& r3) {
    asm volatile("ldmatrix.sync.aligned.m8n8.x4.shared.b16 {%0,%1,%2,%3}, [%4];"
                 : "=r"(r0), "=r"(r1), "=r"(r2), "=r"(r3) : "r"(addr));
}

__device__ __forceinline__ void mma16816(float* d, const u32* a, const u32* b) {
    asm volatile(
        "mma.sync.aligned.m16n8k16.row.col.f32.bf16.bf16.f32 "
        "{%0,%1,%2,%3}, {%4,%5,%6,%7}, {%8,%9}, {%0,%1,%2,%3};"
        : "+f"(d[0]), "+f"(d[1]), "+f"(d[2]), "+f"(d[3])
        : "r"(a[0]), "r"(a[1]), "r"(a[2]), "r"(a[3]), "r"(b[0]), "r"(b[1]));
}

// ----------------------------- smem layout -----------------------------------
// Per stage: Ah | Al | Bh | Bl, each 128 rows x 40 bf16 (80 B pitch; 32 data cols).
// 80 B pitch = 20-bank stride -> ldmatrix conflict-free without swizzle.
#define ROW_PITCH_B 80
#define TILE_BYTES  (128 * ROW_PITCH_B)       // 10240
#define OFF_AH 0
#define OFF_AL (1 * TILE_BYTES)
#define OFF_BH (2 * TILE_BYTES)
#define OFF_BL (3 * TILE_BYTES)
#define STAGE_BYTES (4 * TILE_BYTES)          // 40960
#define SMEM_TOTAL  (2 * STAGE_BYTES)         // 81920

__device__ __forceinline__ void load_stage(
    u32 sb, int tid,
    const __nv_bfloat16* __restrict__ Ahb, const __nv_bfloat16* __restrict__ Alb,
    const __nv_bfloat16* __restrict__ Bhb, const __nv_bfloat16* __restrict__ Blb,
    int row0, int col0, int lda, int ldb, int k0)
{
#pragma unroll
    for (int i = 0; i < 2; i++) {
        const int id = tid + i * 256;         // 512 chunks of 16B per matrix
        const int r  = id >> 2;               // 0..127
        const int c  = id & 3;                // 16B chunk within 64B row
        const u32 dst = r * ROW_PITCH_B + c * 16;
        const size_t ga = (size_t)(row0 + r) * lda + k0 + c * 8;
        const size_t gb = (size_t)(col0 + r) * ldb + k0 + c * 8;
        ldgsts16(sb + OFF_AH + dst, Ahb + ga);
        ldgsts16(sb + OFF_AL + dst, Alb + ga);
        ldgsts16(sb + OFF_BH + dst, Bhb + gb);
        ldgsts16(sb + OFF_BL + dst, Blb + gb);
    }
}

// ----------------------------- main GEMM kernel -------------------------------
// C[M,N] = A[M,K] @ B[N,K]^T, split-bf16 operands (hi/lo), fp32 accumulate.
// EPI: 0 = fp32 row-major, no bias
//      2 = split bf16 row-major + bias
//      3 = split bf16 transposed (C[n][m]) + bias
template <int EPI>
__global__ void __launch_bounds__(256, 1)
mma_gemm(const __nv_bfloat16* __restrict__ Ah, const __nv_bfloat16* __restrict__ Al,
         const __nv_bfloat16* __restrict__ Bh, const __nv_bfloat16* __restrict__ Bl,
         const float* __restrict__ bias,
         float* __restrict__ Cf, __nv_bfloat16* __restrict__ Ch, __nv_bfloat16* __restrict__ Cl,
         int K, int lda, int ldb, int ldc,
         long long sA, long long sB, long long sC)
{
    extern __shared__ char smem[];
    const u32 sb0 = smem_u32(smem);
    const int tid  = threadIdx.x;
    const int lane = tid & 31;
    const int wid  = tid >> 5;
    const int wm   = wid & 3;                 // warp row group (32 rows)
    const int wn   = wid >> 2;                // warp col group (64 cols)
    const int row0 = blockIdx.y * 128;
    const int col0 = blockIdx.x * 128;
    const int z    = blockIdx.z;

    const __nv_bfloat16* Ahb = Ah + (size_t)z * sA;
    const __nv_bfloat16* Alb = Al + (size_t)z * sA;
    const __nv_bfloat16* Bhb = Bh + (size_t)z * sB;
    const __nv_bfloat16* Blb = Bl + (size_t)z * sB;

    float acc[2][8][4];
#pragma unroll
    for (int i = 0; i < 2; i++)
#pragma unroll
        for (int j = 0; j < 8; j++)
#pragma unroll
            for (int e = 0; e < 4; e++) acc[i][j][e] = 0.0f;

    // Precomputed ldmatrix lane addressing offsets
    const u32 a_lane_off = (u32)((lane & 15) * ROW_PITCH_B + (lane >> 4) * 16);
    const u32 b_lane_off = (u32)((((lane >> 4) * 8) + (lane & 7)) * ROW_PITCH_B
                                 + ((lane >> 3) & 1) * 16);

    const int NC = K >> 5;                    // BK = 32

    load_stage(sb0, tid, Ahb, Alb, Bhb, Blb, row0, col0, lda, ldb, 0);
    CP_COMMIT();

    for (int kc = 0; kc < NC; kc++) {
        const u32 sb = sb0 + (kc & 1) * STAGE_BYTES;
        if (kc + 1 < NC) {
            load_stage(sb0 + ((kc + 1) & 1) * STAGE_BYTES, tid,
                       Ahb, Alb, Bhb, Blb, row0, col0, lda, ldb, (kc + 1) * 32);
            CP_COMMIT();
            CP_WAIT(1);
        } else {
            CP_WAIT(0);
        }
        __syncthreads();

#pragma unroll
        for (int ks = 0; ks < 2; ks++) {      // two k16 steps per BK=32
            u32 ah[2][4], al[2][4];
#pragma unroll
            for (int mt = 0; mt < 2; mt++) {
                const u32 abase = sb + (u32)((wm * 32 + mt * 16) * ROW_PITCH_B + ks * 32)
                                  + a_lane_off;
                ldsm4(abase + OFF_AH, ah[mt][0], ah[mt][1], ah[mt][2], ah[mt][3]);
                ldsm4(abase + OFF_AL, al[mt][0], al[mt][1], al[mt][2], al[mt][3]);
            }
#pragma unroll
            for (int bb = 0; bb < 4; bb++) {  // 4 x (n16) blocks = 64 cols
                u32 bh[4], bl[4];
                const u32 bbase = sb + (u32)((wn * 64 + bb * 16) * ROW_PITCH_B + ks * 32)
                                  + b_lane_off;
                ldsm4(bbase + OFF_BH, bh[0], bh[1], bh[2], bh[3]);
                ldsm4(bbase + OFF_BL, bl[0], bl[1], bl[2], bl[3]);
#pragma unroll
                for (int mt = 0; mt < 2; mt++)
#pragma unroll
                    for (int j = 0; j < 2; j++) {
                        float* d = acc[mt][bb * 2 + j];
                        mma16816(d, ah[mt], &bh[2 * j]);
                        mma16816(d, ah[mt], &bl[2 * j]);
                        mma16816(d, al[mt], &bh[2 * j]);
                    }
            }
        }
        __syncthreads();
    }

    // ------------------------------- epilogue --------------------------------
    float*         Cfb = (EPI == 0) ? Cf + (size_t)z * sC : nullptr;
    __nv_bfloat16* Chb = (EPI != 0) ? Ch + (size_t)z * sC : nullptr;
    __nv_bfloat16* Clb = (EPI != 0) ? Cl + (size_t)z * sC : nullptr;

#pragma unroll
    for (int mt = 0; mt < 2; mt++) {
#pragma unroll
        for (int nb = 0; nb < 8; nb++) {
            const int colg = col0 + wn * 64 + nb * 8 + (lane & 3) * 2;
            const size_t r0g = (size_t)row0 + wm * 32 + mt * 16 + (lane >> 2);
            const size_t r1g = r0g + 8;
            float x0 = acc[mt][nb][0], x1 = acc[mt][nb][1];
            float x2 = acc[mt][nb][2], x3 = acc[mt][nb][3];
            if (EPI != 0) {
                const float b0 = __ldg(bias + colg), b1 = __ldg(bias + colg + 1);
                x0 += b0; x1 += b1; x2 += b0; x3 += b1;
            }
            if (EPI == 0) {
                *reinterpret_cast<float2*>(Cfb + r0g * ldc + colg) = make_float2(x0, x1);
                *reinterpret_cast<float2*>(Cfb + r1g * ldc + colg) = make_float2(x2, x3);
            } else {
                __nv_bfloat16 h0 = __float2bfloat16_rn(x0);
                __nv_bfloat16 h1 = __float2bfloat16_rn(x1);
                __nv_bfloat16 h2 = __float2bfloat16_rn(x2);
                __nv_bfloat16 h3 = __float2bfloat16_rn(x3);
                __nv_bfloat16 l0 = __float2bfloat16_rn(x0 - __bfloat162float(h0));
                __nv_bfloat16 l1 = __float2bfloat16_rn(x1 - __bfloat162float(h1));
                __nv_bfloat16 l2 = __float2bfloat16_rn(x2 - __bfloat162float(h2));
                __nv_bfloat16 l3 = __float2bfloat16_rn(x3 - __bfloat162float(h3));
                if (EPI == 2) {
                    *reinterpret_cast<__nv_bfloat162*>(Chb + r0g * ldc + colg) =
                        __nv_bfloat162(h0, h1);
                    *reinterpret_cast<__nv_bfloat162*>(Chb + r1g * ldc + colg) =
                        __nv_bfloat162(h2, h3);
                    *reinterpret_cast<__nv_bfloat162*>(Clb + r0g * ldc + colg) =
                        __nv_bfloat162(l0, l1);
                    *reinterpret_cast<__nv_bfloat162*>(Clb + r1g * ldc + colg) =
                        __nv_bfloat162(l2, l3);
                } else {  // EPI == 3: transposed
                    Chb[(size_t)(colg)     * ldc + r0g] = h0;
                    Chb[(size_t)(colg + 1) * ldc + r0g] = h1;
                    Chb[(size_t)(colg)     * ldc + r1g] = h2;
                    Chb[(size_t)(colg + 1) * ldc + r1g] = h3;
                    Clb[(size_t)(colg)     * ldc + r0g] = l0;
                    Clb[(size_t)(colg + 1) * ldc + r0g] = l1;
                    Clb[(size_t)(colg)     * ldc + r1g] = l2;
                    Clb[(size_t)(colg + 1) * ldc + r1g] = l3;
                }
            }
        }
    }
}

// ----------------------------- prep kernels ----------------------------------
__global__ void split_f32(const float* __restrict__ x,
                          __nv_bfloat16* __restrict__ h, __nv_bfloat16* __restrict__ l,
                          size_t n)
{
    size_t i = (size_t)blockIdx.x * blockDim.x + threadIdx.x;
    const size_t stride = (size_t)gridDim.x * blockDim.x;
    for (; i < n; i += stride) {
        float v = x[i];
        __nv_bfloat16 hh = __float2bfloat16_rn(v);
        h[i] = hh;
        l[i] = __float2bfloat16_rn(v - __bfloat162float(hh));
    }
}

// W[K,N] -> T[N,K] split
__global__ void transpose_split(const float* __restrict__ W,
                                __nv_bfloat16* __restrict__ Th, __nv_bfloat16* __restrict__ Tl,
                                int K, int N)
{
    __shared__ float t[32][33];
    const int bx = blockIdx.x * 32;  // N
    const int by = blockIdx.y * 32;  // K
    const int tx = threadIdx.x, ty = threadIdx.y;
    for (int r = ty; r < 32; r += 8)
        t[r][tx] = W[(size_t)(by + r) * N + bx + tx];
    __syncthreads();
    for (int r = ty; r < 32; r += 8) {
        const float x = t[tx][r];
        __nv_bfloat16 h = __float2bfloat16_rn(x);
        Th[(size_t)(bx + r) * K + by + tx] = h;
        Tl[(size_t)(bx + r) * K + by + tx] = __float2bfloat16_rn(x - __bfloat162float(h));
    }
}

// softmax over 2304-wide rows + split bf16 output
__global__ void __launch_bounds__(256)
softmax_split(const float* __restrict__ adj,
              __nv_bfloat16* __restrict__ ph, __nv_bfloat16* __restrict__ pl)
{
    const size_t base = (size_t)blockIdx.x * NTOK;
    const int t = threadIdx.x;
    __shared__ float red[256];

    float v[9];
    float m = -CUDART_INF_F;
#pragma unroll
    for (int i = 0; i < 9; i++) {
        v[i] = adj[base + t + i * 256];
        m = fmaxf(m, v[i]);
    }
    red[t] = m;
    __syncthreads();
#pragma unroll
    for (int s = 128; s > 0; s >>= 1) {
        if (t < s) red[t] = fmaxf(red[t], red[t + s]);
        __syncthreads();
    }
    m = red[0];
    __syncthreads();

    float sum = 0.0f;
#pragma unroll
    for (int i = 0; i < 9; i++) {
        v[i] = __expf(v[i] - m);
        sum += v[i];
    }
    red[t] = sum;
    __syncthreads();
#pragma unroll
    for (int s = 128; s > 0; s >>= 1) {
        if (t < s) red[t] += red[t + s];
        __syncthreads();
    }
    const float inv = 1.0f / red[0];
#pragma unroll
    for (int i = 0; i < 9; i++) {
        const float p = v[i] * inv;
        __nv_bfloat16 h = __float2bfloat16_rn(p);
        ph[base + t + i * 256] = h;
        pl[base + t + i * 256] = __float2bfloat16_rn(p - __bfloat162float(h));
    }
}

// ----------------------------- launcher --------------------------------------
extern "C" void kernel_launch(void* const* d_in, const int* in_sizes, int n_in,
                              void* d_out, int out_size)
{
    const float* feats = (const float*)d_in[0];
    const float* Wq    = (const float*)d_in[1];
    const float* bq    = (const float*)d_in[2];
    const float* Wk    = (const float*)d_in[3];
    const float* bk    = (const float*)d_in[4];
    const float* Wu    = (const float*)d_in[5];
    const float* bu    = (const float*)d_in[6];
    float*       out   = (float*)d_out;

    __nv_bfloat16 *fh, *fl, *wqh, *wql, *wkh, *wkl, *wuh, *wul;
    __nv_bfloat16 *qh, *ql, *kh, *kl, *vth, *vtl, *php, *plp;
    float *adjp;
    cudaGetSymbolAddress((void**)&fh,  g_fh);  cudaGetSymbolAddress((void**)&fl,  g_fl);
    cudaGetSymbolAddress((void**)&wqh, g_wqh); cudaGetSymbolAddress((void**)&wql, g_wql);
    cudaGetSymbolAddress((void**)&wkh, g_wkh); cudaGetSymbolAddress((void**)&wkl, g_wkl);
    cudaGetSymbolAddress((void**)&wuh, g_wuh); cudaGetSymbolAddress((void**)&wul, g_wul);
    cudaGetSymbolAddress((void**)&qh,  g_qh);  cudaGetSymbolAddress((void**)&ql,  g_ql);
    cudaGetSymbolAddress((void**)&kh,  g_kh);  cudaGetSymbolAddress((void**)&kl,  g_kl);
    cudaGetSymbolAddress((void**)&vth, g_vth); cudaGetSymbolAddress((void**)&vtl, g_vtl);
    cudaGetSymbolAddress((void**)&php, g_ph);  cudaGetSymbolAddress((void**)&plp, g_pl);
    cudaGetSymbolAddress((void**)&adjp, g_adj);

    cudaFuncSetAttribute(mma_gemm<0>, cudaFuncAttributeMaxDynamicSharedMemorySize, SMEM_TOTAL);
    cudaFuncSetAttribute(mma_gemm<2>, cudaFuncAttributeMaxDynamicSharedMemorySize, SMEM_TOTAL);
    cudaFuncSetAttribute(mma_gemm<3>, cudaFuncAttributeMaxDynamicSharedMemorySize, SMEM_TOTAL);

    // prep: split feats, transpose+split weights
    split_f32<<<1024, 256>>>(feats, fh, fl, (size_t)MTOT * DIM);
    transpose_split<<<dim3(DIM / 32, DIM / 32),  dim3(32, 8)>>>(Wq, wqh, wql, DIM, DIM);
    transpose_split<<<dim3(DIM / 32, DIM / 32),  dim3(32, 8)>>>(Wk, wkh, wkl, DIM, DIM);
    transpose_split<<<dim3(VDIM / 32, DIM / 32), dim3(32, 8)>>>(Wu, wuh, wul, DIM, VDIM);

    const dim3 blk(256);
    // q = feats @ Wq^T (+bq) -> split bf16   [9216, 2048]
    mma_gemm<2><<<dim3(DIM / 128, MTOT / 128, 1), blk, SMEM_TOTAL>>>(
        fh, fl, wqh, wql, bq, nullptr, qh, ql, DIM, DIM, DIM, DIM, 0, 0, 0);
    // k
    mma_gemm<2><<<dim3(DIM / 128, MTOT / 128, 1), blk, SMEM_TOTAL>>>(
        fh, fl, wkh, wkl, bk, nullptr, kh, kl, DIM, DIM, DIM, DIM, 0, 0, 0);
    // v (transposed write) [1024, 9216]
    mma_gemm<3><<<dim3(VDIM / 128, MTOT / 128, 1), blk, SMEM_TOTAL>>>(
        fh, fl, wuh, wul, bu, nullptr, vth, vtl, DIM, DIM, DIM, MTOT, 0, 0, 0);
    // adj[b] = q[b] @ k[b]^T  fp32 [2304, 2304] per batch
    mma_gemm<0><<<dim3(NTOK / 128, NTOK / 128, BATCH), blk, SMEM_TOTAL>>>(
        qh, ql, kh, kl, nullptr, adjp, nullptr, nullptr,
        DIM, DIM, DIM, NTOK,
        (long long)NTOK * DIM, (long long)NTOK * DIM, (long long)NTOK * NTOK);
    // softmax -> split P
    softmax_split<<<MTOT, 256>>>(adjp, php, plp);
    // out[b] = P[b] @ v[b]   (B = v^T with per-batch column offset z*NTOK)
    mma_gemm<0><<<dim3(VDIM / 128, NTOK / 128, BATCH), blk, SMEM_TOTAL>>>(
        php, plp, vth, vtl, nullptr, out, nullptr, nullptr,
        NTOK, NTOK, MTOT, VDIM,
        (long long)NTOK * NTOK, (long long)NTOK, (long long)NTOK * VDIM);
}

// round 6
// speedup vs baseline: 1.0013x; 1.0013x over previous
#include <cuda_runtime.h>
#include <cuda_bf16.h>
#include <cstdint>
#include <math_constants.h>

typedef unsigned int u32;

#define BATCH 4
#define NTOK  2304
#define DIM   2048
#define VDIM  1024
#define MTOT  (BATCH * NTOK)   // 9216

// ----------------------------- scratch (allocation-free rule) ---------------
__device__ __nv_bfloat16 g_fh[(size_t)MTOT * DIM];
__device__ __nv_bfloat16 g_fl[(size_t)MTOT * DIM];
__device__ __nv_bfloat16 g_wqh[(size_t)DIM * DIM];
__device__ __nv_bfloat16 g_wql[(size_t)DIM * DIM];
__device__ __nv_bfloat16 g_wkh[(size_t)DIM * DIM];
__device__ __nv_bfloat16 g_wkl[(size_t)DIM * DIM];
__device__ __nv_bfloat16 g_wuh[(size_t)VDIM * DIM];
__device__ __nv_bfloat16 g_wul[(size_t)VDIM * DIM];
__device__ __nv_bfloat16 g_qh[(size_t)MTOT * DIM];
__device__ __nv_bfloat16 g_ql[(size_t)MTOT * DIM];
__device__ __nv_bfloat16 g_kh[(size_t)MTOT * DIM];
__device__ __nv_bfloat16 g_kl[(size_t)MTOT * DIM];
__device__ __nv_bfloat16 g_vth[(size_t)VDIM * MTOT];   // v^T [VDIM, MTOT]
__device__ __nv_bfloat16 g_vtl[(size_t)VDIM * MTOT];
__device__ float         g_adj[(size_t)BATCH * NTOK * NTOK];
__device__ __nv_bfloat16 g_ph[(size_t)BATCH * NTOK * NTOK];
__device__ __nv_bfloat16 g_pl[(size_t)BATCH * NTOK * NTOK];

// ----------------------------- helpers --------------------------------------
__device__ __forceinline__ u32 smem_u32(const void* p) {
    u32 a;
    asm("{ .reg .u64 t; cvta.to.shared.u64 t, %1; cvt.u32.u64 %0, t; }"
        : "=r"(a) : "l"(p));
    return a;
}

__device__ __forceinline__ void ldgsts16(u32 dst, const void* src) {
    asm volatile("cp.async.cg.shared.global [%0], [%1], 16;"
                 :: "r"(dst), "l"(src) : "memory");
}
#define CP_COMMIT() asm volatile("cp.async.commit_group;" ::: "memory")
#define CP_WAIT(n)  asm volatile("cp.async.wait_group %0;" :: "n"(n) : "memory")

__device__ __forceinline__ void ldsm4(u32 addr, u32& r0, u32& r1, u32& r2, u32& r3) {
    asm volatile("ldmatrix.sync.aligned.m8n8.x4.shared.b16 {%0,%1,%2,%3}, [%4];"
                 : "=r"(r0), "=r"(r1), "=r"(r2), "=r"(r3) : "r"(addr));
}

__device__ __forceinline__ void mma16816(float* d, const u32* a, const u32* b) {
    asm volatile(
        "mma.sync.aligned.m16n8k16.row.col.f32.bf16.bf16.f32 "
        "{%0,%1,%2,%3}, {%4,%5,%6,%7}, {%8,%9}, {%0,%1,%2,%3};"
        : "+f"(d[0]), "+f"(d[1]), "+f"(d[2]), "+f"(d[3])
        : "r"(a[0]), "r"(a[1]), "r"(a[2]), "r"(a[3]), "r"(b[0]), "r"(b[1]));
}

// ----------------------------- smem layout -----------------------------------
// Per stage: Ah | Al | Bh | Bl, each 128 rows x 40 bf16 (80 B pitch; 32 data cols).
// 80 B pitch = 20-bank stride -> ldmatrix conflict-free without swizzle.
#define ROW_PITCH_B 80
#define TILE_BYTES  (128 * ROW_PITCH_B)       // 10240
#define OFF_AH 0
#define OFF_AL (1 * TILE_BYTES)
#define OFF_BH (2 * TILE_BYTES)
#define OFF_BL (3 * TILE_BYTES)
#define STAGE_BYTES (4 * TILE_BYTES)          // 40960
#define SMEM_TOTAL  (2 * STAGE_BYTES)         // 81920

__device__ __forceinline__ void load_stage(
    u32 sb, int tid,
    const __nv_bfloat16* __restrict__ Ahb, const __nv_bfloat16* __restrict__ Alb,
    const __nv_bfloat16* __restrict__ Bhb, const __nv_bfloat16* __restrict__ Blb,
    int row0, int col0, int lda, int ldb, int k0)
{
#pragma unroll
    for (int i = 0; i < 2; i++) {
        const int id = tid + i * 256;         // 512 chunks of 16B per matrix
        const int r  = id >> 2;               // 0..127
        const int c  = id & 3;                // 16B chunk within 64B row
        const u32 dst = r * ROW_PITCH_B + c * 16;
        const size_t ga = (size_t)(row0 + r) * lda + k0 + c * 8;
        const size_t gb = (size_t)(col0 + r) * ldb + k0 + c * 8;
        ldgsts16(sb + OFF_AH + dst, Ahb + ga);
        ldgsts16(sb + OFF_AL + dst, Alb + ga);
        ldgsts16(sb + OFF_BH + dst, Bhb + gb);
        ldgsts16(sb + OFF_BL + dst, Blb + gb);
    }
}

// ----------------------------- main GEMM kernel -------------------------------
// C[M,N] = A[M,K] @ B[N,K]^T, split-bf16 operands (hi/lo), fp32 accumulate.
// EPI: 0 = fp32 row-major, no bias
//      2 = split bf16 row-major + bias
//      3 = split bf16 transposed (C[n][m]) + bias
template <int EPI>
__global__ void __launch_bounds__(256, 1)
mma_gemm(const __nv_bfloat16* __restrict__ Ah, const __nv_bfloat16* __restrict__ Al,
         const __nv_bfloat16* __restrict__ Bh, const __nv_bfloat16* __restrict__ Bl,
         const float* __restrict__ bias,
         float* __restrict__ Cf, __nv_bfloat16* __restrict__ Ch, __nv_bfloat16* __restrict__ Cl,
         int K, int lda, int ldb, int ldc,
         long long sA, long long sB, long long sC)
{
    extern __shared__ char smem[];
    const u32 sb0 = smem_u32(smem);
    const int tid  = threadIdx.x;
    const int lane = tid & 31;
    const int wid  = tid >> 5;
    const int wm   = wid & 3;                 // warp row group (32 rows)
    const int wn   = wid >> 2;                // warp col group (64 cols)
    const int row0 = blockIdx.y * 128;
    const int col0 = blockIdx.x * 128;
    const int z    = blockIdx.z;

    const __nv_bfloat16* Ahb = Ah + (size_t)z * sA;
    const __nv_bfloat16* Alb = Al + (size_t)z * sA;
    const __nv_bfloat16* Bhb = Bh + (size_t)z * sB;
    const __nv_bfloat16* Blb = Bl + (size_t)z * sB;

    float acc[2][8][4];
#pragma unroll
    for (int i = 0; i < 2; i++)
#pragma unroll
        for (int j = 0; j < 8; j++)
#pragma unroll
            for (int e = 0; e < 4; e++) acc[i][j][e] = 0.0f;

    // Precomputed ldmatrix lane addressing offsets
    const u32 a_lane_off = (u32)((lane & 15) * ROW_PITCH_B + (lane >> 4) * 16);
    const u32 b_lane_off = (u32)((((lane >> 4) * 8) + (lane & 7)) * ROW_PITCH_B
                                 + ((lane >> 3) & 1) * 16);

    const int NC = K >> 5;                    // BK = 32

    load_stage(sb0, tid, Ahb, Alb, Bhb, Blb, row0, col0, lda, ldb, 0);
    CP_COMMIT();

    for (int kc = 0; kc < NC; kc++) {
        const u32 sb = sb0 + (kc & 1) * STAGE_BYTES;
        if (kc + 1 < NC) {
            load_stage(sb0 + ((kc + 1) & 1) * STAGE_BYTES, tid,
                       Ahb, Alb, Bhb, Blb, row0, col0, lda, ldb, (kc + 1) * 32);
            CP_COMMIT();
            CP_WAIT(1);
        } else {
            CP_WAIT(0);
        }
        __syncthreads();

#pragma unroll
        for (int ks = 0; ks < 2; ks++) {      // two k16 steps per BK=32
            u32 ah[2][4], al[2][4];
#pragma unroll
            for (int mt = 0; mt < 2; mt++) {
                const u32 abase = sb + (u32)((wm * 32 + mt * 16) * ROW_PITCH_B + ks * 32)
                                  + a_lane_off;
                ldsm4(abase + OFF_AH, ah[mt][0], ah[mt][1], ah[mt][2], ah[mt][3]);
                ldsm4(abase + OFF_AL, al[mt][0], al[mt][1], al[mt][2], al[mt][3]);
            }
#pragma unroll
            for (int bb = 0; bb < 4; bb++) {  // 4 x (n16) blocks = 64 cols
                u32 bh[4], bl[4];
                const u32 bbase = sb + (u32)((wn * 64 + bb * 16) * ROW_PITCH_B + ks * 32)
                                  + b_lane_off;
                ldsm4(bbase + OFF_BH, bh[0], bh[1], bh[2], bh[3]);
                ldsm4(bbase + OFF_BL, bl[0], bl[1], bl[2], bl[3]);
#pragma unroll
                for (int mt = 0; mt < 2; mt++)
#pragma unroll
                    for (int j = 0; j < 2; j++) {
                        float* d = acc[mt][bb * 2 + j];
                        mma16816(d, ah[mt], &bh[2 * j]);
                        mma16816(d, ah[mt], &bl[2 * j]);
                        mma16816(d, al[mt], &bh[2 * j]);
                    }
            }
        }
        __syncthreads();
    }

    // ------------------------------- epilogue --------------------------------
    float*         Cfb = (EPI == 0) ? Cf + (size_t)z * sC : nullptr;
    __nv_bfloat16* Chb = (EPI != 0) ? Ch + (size_t)z * sC : nullptr;
    __nv_bfloat16* Clb = (EPI != 0) ? Cl + (size_t)z * sC : nullptr;

#pragma unroll
    for (int mt = 0; mt < 2; mt++) {
#pragma unroll
        for (int nb = 0; nb < 8; nb++) {
            const int colg = col0 + wn * 64 + nb * 8 + (lane & 3) * 2;
            const size_t r0g = (size_t)row0 + wm * 32 + mt * 16 + (lane >> 2);
            const size_t r1g = r0g + 8;
            float x0 = acc[mt][nb][0], x1 = acc[mt][nb][1];
            float x2 = acc[mt][nb][2], x3 = acc[mt][nb][3];
            if (EPI != 0) {
                const float b0 = __ldg(bias + colg), b1 = __ldg(bias + colg + 1);
                x0 += b0; x1 += b1; x2 += b0; x3 += b1;
            }
            if (EPI == 0) {
                *reinterpret_cast<float2*>(Cfb + r0g * ldc + colg) = make_float2(x0, x1);
                *reinterpret_cast<float2*>(Cfb + r1g * ldc + colg) = make_float2(x2, x3);
            } else {
                __nv_bfloat16 h0 = __float2bfloat16_rn(x0);
                __nv_bfloat16 h1 = __float2bfloat16_rn(x1);
                __nv_bfloat16 h2 = __float2bfloat16_rn(x2);
                __nv_bfloat16 h3 = __float2bfloat16_rn(x3);
                __nv_bfloat16 l0 = __float2bfloat16_rn(x0 - __bfloat162float(h0));
                __nv_bfloat16 l1 = __float2bfloat16_rn(x1 - __bfloat162float(h1));
                __nv_bfloat16 l2 = __float2bfloat16_rn(x2 - __bfloat162float(h2));
                __nv_bfloat16 l3 = __float2bfloat16_rn(x3 - __bfloat162float(h3));
                if (EPI == 2) {
                    *reinterpret_cast<__nv_bfloat162*>(Chb + r0g * ldc + colg) =
                        __nv_bfloat162(h0, h1);
                    *reinterpret_cast<__nv_bfloat162*>(Chb + r1g * ldc + colg) =
                        __nv_bfloat162(h2, h3);
                    *reinterpret_cast<__nv_bfloat162*>(Clb + r0g * ldc + colg) =
                        __nv_bfloat162(l0, l1);
                    *reinterpret_cast<__nv_bfloat162*>(Clb + r1g * ldc + colg) =
                        __nv_bfloat162(l2, l3);
                } else {  // EPI == 3: transposed
                    Chb[(size_t)(colg)     * ldc + r0g] = h0;
                    Chb[(size_t)(colg + 1) * ldc + r0g] = h1;
                    Chb[(size_t)(colg)     * ldc + r1g] = h2;
                    Chb[(size_t)(colg + 1) * ldc + r1g] = h3;
                    Clb[(size_t)(colg)     * ldc + r0g] = l0;
                    Clb[(size_t)(colg + 1) * ldc + r0g] = l1;
                    Clb[(size_t)(colg)     * ldc + r1g] = l2;
                    Clb[(size_t)(colg + 1) * ldc + r1g] = l3;
                }
            }
        }
    }
}

// ----------------------------- prep kernels ----------------------------------
__global__ void split_f32(const float* __restrict__ x,
                          __nv_bfloat16* __restrict__ h, __nv_bfloat16* __restrict__ l,
                          size_t n)
{
    size_t i = (size_t)blockIdx.x * blockDim.x + threadIdx.x;
    const size_t stride = (size_t)gridDim.x * blockDim.x;
    for (; i < n; i += stride) {
        float v = x[i];
        __nv_bfloat16 hh = __float2bfloat16_rn(v);
        h[i] = hh;
        l[i] = __float2bfloat16_rn(v - __bfloat162float(hh));
    }
}

// W[K,N] -> T[N,K] split
__global__ void transpose_split(const float* __restrict__ W,
                                __nv_bfloat16* __restrict__ Th, __nv_bfloat16* __restrict__ Tl,
                                int K, int N)
{
    __shared__ float t[32][33];
    const int bx = blockIdx.x * 32;  // N
    const int by = blockIdx.y * 32;  // K
    const int tx = threadIdx.x, ty = threadIdx.y;
    for (int r = ty; r < 32; r += 8)
        t[r][tx] = W[(size_t)(by + r) * N + bx + tx];
    __syncthreads();
    for (int r = ty; r < 32; r += 8) {
        const float x = t[tx][r];
        __nv_bfloat16 h = __float2bfloat16_rn(x);
        Th[(size_t)(bx + r) * K + by + tx] = h;
        Tl[(size_t)(bx + r) * K + by + tx] = __float2bfloat16_rn(x - __bfloat162float(h));
    }
}

// softmax over 2304-wide rows + split bf16 output
__global__ void __launch_bounds__(256)
softmax_split(const float* __restrict__ adj,
              __nv_bfloat16* __restrict__ ph, __nv_bfloat16* __restrict__ pl)
{
    const size_t base = (size_t)blockIdx.x * NTOK;
    const int t = threadIdx.x;
    __shared__ float red[256];

    float v[9];
    float m = -CUDART_INF_F;
#pragma unroll
    for (int i = 0; i < 9; i++) {
        v[i] = adj[base + t + i * 256];
        m = fmaxf(m, v[i]);
    }
    red[t] = m;
    __syncthreads();
#pragma unroll
    for (int s = 128; s > 0; s >>= 1) {
        if (t < s) red[t] = fmaxf(red[t], red[t + s]);
        __syncthreads();
    }
    m = red[0];
    __syncthreads();

    float sum = 0.0f;
#pragma unroll
    for (int i = 0; i < 9; i++) {
        v[i] = __expf(v[i] - m);
        sum += v[i];
    }
    red[t] = sum;
    __syncthreads();
#pragma unroll
    for (int s = 128; s > 0; s >>= 1) {
        if (t < s) red[t] += red[t + s];
        __syncthreads();
    }
    const float inv = 1.0f / red[0];
#pragma unroll
    for (int i = 0; i < 9; i++) {
        const float p = v[i] * inv;
        __nv_bfloat16 h = __float2bfloat16_rn(p);
        ph[base + t + i * 256] = h;
        pl[base + t + i * 256] = __float2bfloat16_rn(p - __bfloat162float(h));
    }
}

// ----------------------------- launcher --------------------------------------
extern "C" void kernel_launch(void* const* d_in, const int* in_sizes, int n_in,
                              void* d_out, int out_size)
{
    const float* feats = (const float*)d_in[0];
    const float* Wq    = (const float*)d_in[1];
    const float* bq    = (const float*)d_in[2];
    const float* Wk    = (const float*)d_in[3];
    const float* bk    = (const float*)d_in[4];
    const float* Wu    = (const float*)d_in[5];
    const float* bu    = (const float*)d_in[6];
    float*       out   = (float*)d_out;

    __nv_bfloat16 *fh, *fl, *wqh, *wql, *wkh, *wkl, *wuh, *wul;
    __nv_bfloat16 *qh, *ql, *kh, *kl, *vth, *vtl, *php, *plp;
    float *adjp;
    cudaGetSymbolAddress((void**)&fh,  g_fh);  cudaGetSymbolAddress((void**)&fl,  g_fl);
    cudaGetSymbolAddress((void**)&wqh, g_wqh); cudaGetSymbolAddress((void**)&wql, g_wql);
    cudaGetSymbolAddress((void**)&wkh, g_wkh); cudaGetSymbolAddress((void**)&wkl, g_wkl);
    cudaGetSymbolAddress((void**)&wuh, g_wuh); cudaGetSymbolAddress((void**)&wul, g_wul);
    cudaGetSymbolAddress((void**)&qh,  g_qh);  cudaGetSymbolAddress((void**)&ql,  g_ql);
    cudaGetSymbolAddress((void**)&kh,  g_kh);  cudaGetSymbolAddress((void**)&kl,  g_kl);
    cudaGetSymbolAddress((void**)&vth, g_vth); cudaGetSymbolAddress((void**)&vtl, g_vtl);
    cudaGetSymbolAddress((void**)&php, g_ph);  cudaGetSymbolAddress((void**)&plp, g_pl);
    cudaGetSymbolAddress((void**)&adjp, g_adj);

    cudaFuncSetAttribute(mma_gemm<0>, cudaFuncAttributeMaxDynamicSharedMemorySize, SMEM_TOTAL);
    cudaFuncSetAttribute(mma_gemm<2>, cudaFuncAttributeMaxDynamicSharedMemorySize, SMEM_TOTAL);
    cudaFuncSetAttribute(mma_gemm<3>, cudaFuncAttributeMaxDynamicSharedMemorySize, SMEM_TOTAL);

    // prep: split feats, transpose+split weights
    split_f32<<<1024, 256>>>(feats, fh, fl, (size_t)MTOT * DIM);
    transpose_split<<<dim3(DIM / 32, DIM / 32),  dim3(32, 8)>>>(Wq, wqh, wql, DIM, DIM);
    transpose_split<<<dim3(DIM / 32, DIM / 32),  dim3(32, 8)>>>(Wk, wkh, wkl, DIM, DIM);
    transpose_split<<<dim3(VDIM / 32, DIM / 32), dim3(32, 8)>>>(Wu, wuh, wul, DIM, VDIM);

    const dim3 blk(256);
    // q = feats @ Wq^T (+bq) -> split bf16   [9216, 2048]
    mma_gemm<2><<<dim3(DIM / 128, MTOT / 128, 1), blk, SMEM_TOTAL>>>(
        fh, fl, wqh, wql, bq, nullptr, qh, ql, DIM, DIM, DIM, DIM, 0, 0, 0);
    // k
    mma_gemm<2><<<dim3(DIM / 128, MTOT / 128, 1), blk, SMEM_TOTAL>>>(
        fh, fl, wkh, wkl, bk, nullptr, kh, kl, DIM, DIM, DIM, DIM, 0, 0, 0);
    // v (transposed write) [1024, 9216]
    mma_gemm<3><<<dim3(VDIM / 128, MTOT / 128, 1), blk, SMEM_TOTAL>>>(
        fh, fl, wuh, wul, bu, nullptr, vth, vtl, DIM, DIM, DIM, MTOT, 0, 0, 0);
    // adj[b] = q[b] @ k[b]^T  fp32 [2304, 2304] per batch
    mma_gemm<0><<<dim3(NTOK / 128, NTOK / 128, BATCH), blk, SMEM_TOTAL>>>(
        qh, ql, kh, kl, nullptr, adjp, nullptr, nullptr,
        DIM, DIM, DIM, NTOK,
        (long long)NTOK * DIM, (long long)NTOK * DIM, (long long)NTOK * NTOK);
    // softmax -> split P
    softmax_split<<<MTOT, 256>>>(adjp, php, plp);
    // out[b] = P[b] @ v[b]   (B = v^T with per-batch column offset z*NTOK)
    mma_gemm<0><<<dim3(VDIM / 128, NTOK / 128, BATCH), blk, SMEM_TOTAL>>>(
        php, plp, vth, vtl, nullptr, out, nullptr, nullptr,
        NTOK, NTOK, MTOT, VDIM,
        (long long)NTOK * NTOK, (long long)NTOK, (long long)NTOK * VDIM);
}